// round 7
// baseline (speedup 1.0000x reference)
#include <cuda_runtime.h>
#include <cuda_bf16.h>
#include <math.h>
#include <stdint.h>

// ---------------- problem constants ----------------
#define BATCH 48
#define HH 49
#define WW2 49
#define CC 128
#define LL (HH * WW2)            // 2401
#define NHEAD 4
#define HD 32
#define WS 7
#define SS 3
#define NWIN 49
#define NTOK 49
#define NPAD 52                  // NTOK padded to mult of 4
#define MTOT (BATCH * LL)        // 115248
#define HID 512

// ---------------- scratch (device globals; no allocations) ----------------
__device__ __nv_bfloat16 g_xw[(size_t)MTOT * CC];
__device__ __nv_bfloat16 g_qkvb[(size_t)MTOT * 3 * CC];
__device__ __nv_bfloat16 g_attn[(size_t)MTOT * CC];
__device__ __nv_bfloat16 g_ln2b[(size_t)MTOT * CC];
__device__ __nv_bfloat16 g_h1[(size_t)MTOT * HID];
__device__ float         g_x2[(size_t)MTOT * CC];
__device__ __nv_bfloat16 g_wqkv[384 * 128];
__device__ __nv_bfloat16 g_wproj[128 * 128];
__device__ __nv_bfloat16 g_wfc1[512 * 128];
__device__ __nv_bfloat16 g_wfc2[128 * 512];
__device__ float         g_bias[NWIN * NHEAD * NTOK * NPAD];   // combined rpb + shift mask

// ================= PTX helpers =================
__device__ __forceinline__ uint32_t smem_u32(const void* p) {
    uint32_t a;
    asm("{ .reg .u64 t; cvta.to.shared.u64 t, %1; cvt.u32.u64 %0, t; }" : "=r"(a) : "l"(p));
    return a;
}
__device__ __forceinline__ void mma_bf16(float* c, uint32_t a0, uint32_t a1, uint32_t a2,
                                         uint32_t a3, uint32_t b0, uint32_t b1) {
    asm volatile("mma.sync.aligned.m16n8k16.row.col.f32.bf16.bf16.f32 "
                 "{%0,%1,%2,%3}, {%4,%5,%6,%7}, {%8,%9}, {%0,%1,%2,%3};"
                 : "+f"(c[0]), "+f"(c[1]), "+f"(c[2]), "+f"(c[3])
                 : "r"(a0), "r"(a1), "r"(a2), "r"(a3), "r"(b0), "r"(b1));
}
__device__ __forceinline__ void ldmx4(uint32_t* r, uint32_t addr) {
    asm volatile("ldmatrix.sync.aligned.m8n8.x4.shared.b16 {%0,%1,%2,%3}, [%4];"
                 : "=r"(r[0]), "=r"(r[1]), "=r"(r[2]), "=r"(r[3]) : "r"(addr));
}
__device__ __forceinline__ void cp_async16(uint32_t dst, const void* src, int srcsize) {
    asm volatile("cp.async.cg.shared.global [%0], [%1], 16, %2;"
                 :: "r"(dst), "l"(src), "r"(srcsize) : "memory");
}
#define CP_COMMIT() asm volatile("cp.async.commit_group;" ::: "memory")
#define CP_WAIT(n)  asm volatile("cp.async.wait_group %0;" :: "n"(n) : "memory")

// ---------------- fused weight conversion (one launch) ----------------
#define NW1 (384 * 128)
#define NW2 (128 * 128)
#define NW3 (512 * 128)
#define NW4 (128 * 512)
__global__ void cvt_all_kernel(const float* __restrict__ s1, const float* __restrict__ s2,
                               const float* __restrict__ s3, const float* __restrict__ s4,
                               __nv_bfloat16* __restrict__ d1, __nv_bfloat16* __restrict__ d2,
                               __nv_bfloat16* __restrict__ d3, __nv_bfloat16* __restrict__ d4) {
    int i = blockIdx.x * 256 + threadIdx.x;
    if (i < NW1) { d1[i] = __float2bfloat16(s1[i]); return; }
    i -= NW1;
    if (i < NW2) { d2[i] = __float2bfloat16(s2[i]); return; }
    i -= NW2;
    if (i < NW3) { d3[i] = __float2bfloat16(s3[i]); return; }
    i -= NW3;
    if (i < NW4) { d4[i] = __float2bfloat16(s4[i]); }
}

// ---------------- combined rpb bias + shift mask table ----------------
__device__ __forceinline__ int region1d(int p) {
    return (p < HH - WS) ? 0 : ((p < HH - SS) ? 1 : 2);
}
__global__ void biasmask_kernel(const float* __restrict__ rpb, float* __restrict__ out) {
    int w = blockIdx.x, h = blockIdx.y;
    int wh = w / 7, wwc = w % 7;
    for (int idx = threadIdx.x; idx < NTOK * NPAD; idx += 256) {
        int n = idx / NPAD, m = idx % NPAD;
        float v;
        if (m >= NTOK) {
            v = -1e30f;
        } else {
            int ni = n / 7, nj = n % 7, mi = m / 7, mj = m % 7;
            int rel = (ni - mi + WS - 1) * (2 * WS - 1) + (nj - mj + WS - 1);
            v = rpb[rel * NHEAD + h];
            int r1 = 3 * region1d(wh * 7 + mi) + region1d(wwc * 7 + mj);
            int r2 = 3 * region1d(ni * 7 + mi) + region1d(nj * 7 + mj);
            if (r1 != r2) v -= 100.0f;
        }
        out[((size_t)(w * NHEAD + h) * NTOK) * NPAD + idx] = v;
    }
}

// ---------------- LN1 + cyclic shift + window partition (warp per row) ----------------
__global__ void __launch_bounds__(256) ln1_kernel(const float* __restrict__ x,
                                                  const float* __restrict__ gw,
                                                  const float* __restrict__ gb,
                                                  __nv_bfloat16* __restrict__ xw) {
    int warp = threadIdx.x >> 5, lane = threadIdx.x & 31;
    int gid = blockIdx.x * 8 + warp;
    int b = gid / (NWIN * NTOK);
    int r = gid % (NWIN * NTOK);
    int w = r / NTOK, n = r % NTOK;
    int i = (w / 7) * 7 + n / 7, j = (w % 7) * 7 + n % 7;
    int si = (i + SS) % HH, sj = (j + SS) % WW2;
    float4 v = ((const float4*)(x + ((size_t)b * LL + (size_t)si * WW2 + sj) * CC))[lane];
    float s  = v.x + v.y + v.z + v.w;
    float s2 = v.x * v.x + v.y * v.y + v.z * v.z + v.w * v.w;
    #pragma unroll
    for (int o = 16; o; o >>= 1) {
        s  += __shfl_xor_sync(0xFFFFFFFFu, s,  o);
        s2 += __shfl_xor_sync(0xFFFFFFFFu, s2, o);
    }
    float mean = s * (1.0f / CC);
    float var  = s2 * (1.0f / CC) - mean * mean;
    float rstd = rsqrtf(var + 1e-5f);
    float4 gwv = ((const float4*)gw)[lane];
    float4 gbv = ((const float4*)gb)[lane];
    float o0 = (v.x - mean) * rstd * gwv.x + gbv.x;
    float o1 = (v.y - mean) * rstd * gwv.y + gbv.y;
    float o2 = (v.z - mean) * rstd * gwv.z + gbv.z;
    float o3 = (v.w - mean) * rstd * gwv.w + gbv.w;
    __nv_bfloat162 p0 = __float22bfloat162_rn(make_float2(o0, o1));
    __nv_bfloat162 p1 = __float22bfloat162_rn(make_float2(o2, o3));
    ((uint2*)(xw + (size_t)gid * CC))[lane] = make_uint2(*(uint32_t*)&p0, *(uint32_t*)&p1);
}

// ---------------- fused merge (window reverse + unshift + residual) + LN2 ----------------
__global__ void __launch_bounds__(256) merge_ln2_kernel(const float* __restrict__ x,
                                                        const __nv_bfloat16* __restrict__ proj,
                                                        const float* __restrict__ gw,
                                                        const float* __restrict__ gb,
                                                        float* __restrict__ x2,
                                                        __nv_bfloat16* __restrict__ ln2b) {
    int warp = threadIdx.x >> 5, lane = threadIdx.x & 31;
    int gid = blockIdx.x * 8 + warp;
    int b = gid / LL, l = gid % LL;
    int i = l / WW2, j = l % WW2;
    int pi = (i + HH - SS) % HH;
    int pj = (j + WW2 - SS) % WW2;
    int w = (pi / 7) * 7 + (pj / 7);
    int n = (pi % 7) * 7 + (pj % 7);
    float4 xv = ((const float4*)(x + (size_t)gid * CC))[lane];
    uint2 pv = ((const uint2*)(proj + (((size_t)b * NWIN + w) * NTOK + n) * CC))[lane];
    __nv_bfloat162 q0 = *(__nv_bfloat162*)&pv.x;
    __nv_bfloat162 q1 = *(__nv_bfloat162*)&pv.y;
    float4 v = make_float4(xv.x + __bfloat162float(q0.x), xv.y + __bfloat162float(q0.y),
                           xv.z + __bfloat162float(q1.x), xv.w + __bfloat162float(q1.y));
    ((float4*)(x2 + (size_t)gid * CC))[lane] = v;

    float s  = v.x + v.y + v.z + v.w;
    float s2 = v.x * v.x + v.y * v.y + v.z * v.z + v.w * v.w;
    #pragma unroll
    for (int o = 16; o; o >>= 1) {
        s  += __shfl_xor_sync(0xFFFFFFFFu, s,  o);
        s2 += __shfl_xor_sync(0xFFFFFFFFu, s2, o);
    }
    float mean = s * (1.0f / CC);
    float var  = s2 * (1.0f / CC) - mean * mean;
    float rstd = rsqrtf(var + 1e-5f);
    float4 gwv = ((const float4*)gw)[lane];
    float4 gbv = ((const float4*)gb)[lane];
    float o0 = (v.x - mean) * rstd * gwv.x + gbv.x;
    float o1 = (v.y - mean) * rstd * gwv.y + gbv.y;
    float o2 = (v.z - mean) * rstd * gwv.z + gbv.z;
    float o3 = (v.w - mean) * rstd * gwv.w + gbv.w;
    __nv_bfloat162 p0 = __float22bfloat162_rn(make_float2(o0, o1));
    __nv_bfloat162 p1 = __float22bfloat162_rn(make_float2(o2, o3));
    ((uint2*)(ln2b + (size_t)gid * CC))[lane] = make_uint2(*(uint32_t*)&p0, *(uint32_t*)&p1);
}

// ---------------- fused window attention (vectorized, precomputed bias) ----------------
__global__ void __launch_bounds__(256) attn_kernel(const __nv_bfloat16* __restrict__ qkv,
                                                   const float* __restrict__ biasT,
                                                   __nv_bfloat16* __restrict__ out) {
    int bw = blockIdx.x;
    int h  = blockIdx.y;
    int w  = bw % NWIN;

    __shared__ float sq[NTOK * HD];
    __shared__ float skT[HD * NPAD];
    __shared__ float sv[NTOK * HD];
    __shared__ float ss[NTOK * NPAD];

    int tid = threadIdx.x;
    const float scale = 0.17677669529663687f;
    size_t base = (size_t)bw * NTOK * (3 * CC);

    for (int i = tid; i < NTOK * HD; i += 256) {
        int n = i >> 5, d = i & 31;
        const __nv_bfloat16* row = qkv + base + (size_t)n * (3 * CC) + h * HD + d;
        sq[i] = __bfloat162float(row[0]) * scale;
        skT[d * NPAD + n] = __bfloat162float(row[CC]);
        sv[i] = __bfloat162float(row[2 * CC]);
    }
    // zero the padded K columns
    if (tid < HD * (NPAD - NTOK)) {
        int d = tid / (NPAD - NTOK), m = NTOK + tid % (NPAD - NTOK);
        skT[d * NPAD + m] = 0.f;
    }
    __syncthreads();

    const float* brow = biasT + (size_t)(w * NHEAD + h) * NTOK * NPAD;

    // QK^T + bias(+mask), 4 m per item
    for (int it = tid; it < NTOK * (NPAD / 4); it += 256) {
        int n = it / (NPAD / 4), m0 = (it % (NPAD / 4)) * 4;
        float4 acc = *(const float4*)(brow + n * NPAD + m0);
        const float* qn = sq + n * HD;
        #pragma unroll
        for (int d = 0; d < HD; d++) {
            float q = qn[d];
            float4 k = *(const float4*)(skT + d * NPAD + m0);
            acc.x += q * k.x; acc.y += q * k.y; acc.z += q * k.z; acc.w += q * k.w;
        }
        *(float4*)(ss + n * NPAD + m0) = acc;
    }
    __syncthreads();

    // softmax per row
    int warp = tid >> 5, lane = tid & 31;
    for (int n = warp; n < NTOK; n += 8) {
        float v0 = ss[n * NPAD + lane];
        float v1 = (lane + 32 < NTOK) ? ss[n * NPAD + lane + 32] : -1e30f;
        float mx = fmaxf(v0, v1);
        #pragma unroll
        for (int o = 16; o; o >>= 1) mx = fmaxf(mx, __shfl_xor_sync(0xFFFFFFFFu, mx, o));
        float e0 = __expf(v0 - mx);
        float e1 = (lane + 32 < NTOK) ? __expf(v1 - mx) : 0.f;
        float sum = e0 + e1;
        #pragma unroll
        for (int o = 16; o; o >>= 1) sum += __shfl_xor_sync(0xFFFFFFFFu, sum, o);
        float inv = 1.0f / sum;
        ss[n * NPAD + lane] = e0 * inv;
        if (lane + 32 < NTOK) ss[n * NPAD + lane + 32] = e1 * inv;
    }
    __syncthreads();

    // PV: 4 d per item
    for (int it = tid; it < NTOK * (HD / 4); it += 256) {
        int n = it >> 3, d4 = (it & 7) * 4;
        float4 acc = make_float4(0.f, 0.f, 0.f, 0.f);
        const float* pn = ss + n * NPAD;
        #pragma unroll
        for (int m = 0; m < NTOK; m++) {
            float p = pn[m];
            float4 vv = *(const float4*)(sv + m * HD + d4);
            acc.x += p * vv.x; acc.y += p * vv.y; acc.z += p * vv.z; acc.w += p * vv.w;
        }
        __nv_bfloat162 p0 = __float22bfloat162_rn(make_float2(acc.x, acc.y));
        __nv_bfloat162 p1 = __float22bfloat162_rn(make_float2(acc.z, acc.w));
        *(uint2*)(out + ((size_t)bw * NTOK + n) * CC + h * HD + d4) =
            make_uint2(*(uint32_t*)&p0, *(uint32_t*)&p1);
    }
}

// ---------------- bf16 HMMA GEMM (unchanged from R4) ----------------
#define GSMEM 65536
template <int EPI>
__global__ void __launch_bounds__(256) gemm_mma(
    const __nv_bfloat16* __restrict__ A, const __nv_bfloat16* __restrict__ W,
    const float* __restrict__ bias, void* __restrict__ Cout,
    int M, int N, int K, const float* __restrict__ res)
{
    extern __shared__ char smem[];
    uint32_t sb = smem_u32(smem);
    const int tid = threadIdx.x, warp = tid >> 5, lane = tid & 31;
    const int wm = warp >> 2, wn = warp & 3;
    const int m0 = blockIdx.x * 128, n0 = blockIdx.y * 128;
    const uint32_t sA[2] = {sb, sb + 16384u};
    const uint32_t sB[2] = {sb + 32768u, sb + 49152u};
    const int nch = K >> 6;
    const int lrow = tid >> 3;
    const int lck  = tid & 7;

    float acc[4][4][4];
    #pragma unroll
    for (int a = 0; a < 4; a++)
        #pragma unroll
        for (int b = 0; b < 4; b++)
            #pragma unroll
            for (int c = 0; c < 4; c++) acc[a][b][c] = 0.f;

    const int idx = lane >> 3, l8 = lane & 7;
    const int a_rowb = wm * 64 + (idx & 1) * 8 + l8;
    const int a_kb   = (idx >> 1) * 16;
    const int b_rowb = wn * 32 + (idx >> 1) * 8 + l8;
    const int b_kb   = (idx & 1) * 16;
    const uint32_t swz = (uint32_t)(l8 << 4);

    auto load_chunk = [&](int ch) {
        int buf = ch & 1, k0 = ch << 6;
        const __nv_bfloat16* Ag = A + (size_t)m0 * K + k0;
        #pragma unroll
        for (int it = 0; it < 4; it++) {
            int row = lrow + it * 32;
            int sz = (m0 + row < M) ? 16 : 0;
            uint32_t dst = sA[buf] + row * 128 + ((lck * 16) ^ ((row & 7) << 4));
            cp_async16(dst, Ag + (size_t)row * K + lck * 8, sz);
        }
        const __nv_bfloat16* Wg = W + (size_t)n0 * K + k0;
        #pragma unroll
        for (int it = 0; it < 4; it++) {
            int row = lrow + it * 32;
            uint32_t dst = sB[buf] + row * 128 + ((lck * 16) ^ ((row & 7) << 4));
            cp_async16(dst, Wg + (size_t)row * K + lck * 8, 16);
        }
        CP_COMMIT();
    };

    load_chunk(0);
    for (int ch = 0; ch < nch; ch++) {
        if (ch + 1 < nch) { load_chunk(ch + 1); CP_WAIT(1); }
        else              { CP_WAIT(0); }
        __syncthreads();
        int buf = ch & 1;
        uint32_t Abase = sA[buf] + a_rowb * 128;
        uint32_t Bbase = sB[buf] + b_rowb * 128;
        #pragma unroll
        for (int ks = 0; ks < 4; ks++) {
            uint32_t af[4][4], bg[2][4];
            #pragma unroll
            for (int mt = 0; mt < 4; mt++)
                ldmx4(af[mt], Abase + mt * 16 * 128 + (((uint32_t)(ks * 32 + a_kb)) ^ swz));
            #pragma unroll
            for (int np = 0; np < 2; np++)
                ldmx4(bg[np], Bbase + np * 16 * 128 + (((uint32_t)(ks * 32 + b_kb)) ^ swz));
            #pragma unroll
            for (int mt = 0; mt < 4; mt++)
                #pragma unroll
                for (int nt = 0; nt < 4; nt++)
                    mma_bf16(acc[mt][nt],
                             af[mt][0], af[mt][1], af[mt][2], af[mt][3],
                             bg[nt >> 1][(nt & 1) * 2], bg[nt >> 1][(nt & 1) * 2 + 1]);
        }
        __syncthreads();
    }

    const int erow = m0 + wm * 64 + (lane >> 2);
    const int ecol = n0 + wn * 32 + (lane & 3) * 2;
    #pragma unroll
    for (int mt = 0; mt < 4; mt++) {
        #pragma unroll
        for (int nt = 0; nt < 4; nt++) {
            int row = erow + mt * 16;
            int col = ecol + nt * 8;
            float b0 = bias[col], b1 = bias[col + 1];
            float v0 = acc[mt][nt][0] + b0, v1 = acc[mt][nt][1] + b1;
            float v2 = acc[mt][nt][2] + b0, v3 = acc[mt][nt][3] + b1;
            if (EPI == 1) {
                v0 = 0.5f * v0 * (1.0f + erff(v0 * 0.70710678118654752f));
                v1 = 0.5f * v1 * (1.0f + erff(v1 * 0.70710678118654752f));
                v2 = 0.5f * v2 * (1.0f + erff(v2 * 0.70710678118654752f));
                v3 = 0.5f * v3 * (1.0f + erff(v3 * 0.70710678118654752f));
            }
            if (EPI == 2) {
                float* C = (float*)Cout;
                if (row < M) {
                    float2 rr = *(const float2*)(res + (size_t)row * N + col);
                    *(float2*)(C + (size_t)row * N + col) = make_float2(v0 + rr.x, v1 + rr.y);
                }
                if (row + 8 < M) {
                    float2 rr = *(const float2*)(res + (size_t)(row + 8) * N + col);
                    *(float2*)(C + (size_t)(row + 8) * N + col) = make_float2(v2 + rr.x, v3 + rr.y);
                }
            } else {
                __nv_bfloat16* C = (__nv_bfloat16*)Cout;
                if (row < M) {
                    __nv_bfloat162 p = __float22bfloat162_rn(make_float2(v0, v1));
                    *(__nv_bfloat162*)(C + (size_t)row * N + col) = p;
                }
                if (row + 8 < M) {
                    __nv_bfloat162 p = __float22bfloat162_rn(make_float2(v2, v3));
                    *(__nv_bfloat162*)(C + (size_t)(row + 8) * N + col) = p;
                }
            }
        }
    }
}

// ---------------- launch ----------------
extern "C" void kernel_launch(void* const* d_in, const int* in_sizes, int n_in,
                              void* d_out, int out_size) {
    const float* x      = (const float*)d_in[0];
    const float* n1w    = (const float*)d_in[1];
    const float* n1b    = (const float*)d_in[2];
    const float* qkv_w  = (const float*)d_in[3];
    const float* qkv_b  = (const float*)d_in[4];
    const float* proj_w = (const float*)d_in[5];
    const float* proj_b = (const float*)d_in[6];
    const float* rpb    = (const float*)d_in[7];
    const float* n2w    = (const float*)d_in[8];
    const float* n2b    = (const float*)d_in[9];
    const float* fc1_w  = (const float*)d_in[10];
    const float* fc1_b  = (const float*)d_in[11];
    const float* fc2_w  = (const float*)d_in[12];
    const float* fc2_b  = (const float*)d_in[13];
    float* out = (float*)d_out;

    __nv_bfloat16 *xw, *qkvb, *attn, *ln2b, *h1, *wqkv, *wproj, *wfc1, *wfc2;
    float *x2, *biasT;
    cudaGetSymbolAddress((void**)&xw,    g_xw);
    cudaGetSymbolAddress((void**)&qkvb,  g_qkvb);
    cudaGetSymbolAddress((void**)&attn,  g_attn);
    cudaGetSymbolAddress((void**)&ln2b,  g_ln2b);
    cudaGetSymbolAddress((void**)&h1,    g_h1);
    cudaGetSymbolAddress((void**)&x2,    g_x2);
    cudaGetSymbolAddress((void**)&wqkv,  g_wqkv);
    cudaGetSymbolAddress((void**)&wproj, g_wproj);
    cudaGetSymbolAddress((void**)&wfc1,  g_wfc1);
    cudaGetSymbolAddress((void**)&wfc2,  g_wfc2);
    cudaGetSymbolAddress((void**)&biasT, g_bias);

    cudaFuncSetAttribute(gemm_mma<0>, cudaFuncAttributeMaxDynamicSharedMemorySize, GSMEM);
    cudaFuncSetAttribute(gemm_mma<1>, cudaFuncAttributeMaxDynamicSharedMemorySize, GSMEM);
    cudaFuncSetAttribute(gemm_mma<2>, cudaFuncAttributeMaxDynamicSharedMemorySize, GSMEM);

    const int MT = (MTOT + 127) / 128;   // 901

    // 0) weight conversion + bias/mask table (both tiny)
    cvt_all_kernel<<<(NW1 + NW2 + NW3 + NW4 + 255) / 256, 256>>>(
        qkv_w, proj_w, fc1_w, fc2_w, wqkv, wproj, wfc1, wfc2);
    biasmask_kernel<<<dim3(NWIN, NHEAD), 256>>>(rpb, biasT);
    // 1) LN1 + shift + window partition
    ln1_kernel<<<MTOT / 8, 256>>>(x, n1w, n1b, xw);
    // 2) QKV GEMM
    gemm_mma<0><<<dim3(MT, 3), 256, GSMEM>>>(xw, wqkv, qkv_b, qkvb, MTOT, 384, CC, nullptr);
    // 3) fused window attention
    attn_kernel<<<dim3(BATCH * NWIN, NHEAD), 256>>>(qkvb, biasT, attn);
    // 4) proj GEMM (reuse xw as output)
    gemm_mma<0><<<dim3(MT, 1), 256, GSMEM>>>(attn, wproj, proj_b, xw, MTOT, CC, CC, nullptr);
    // 5) merge + residual + LN2 (fused)
    merge_ln2_kernel<<<MTOT / 8, 256>>>(x, xw, n2w, n2b, x2, ln2b);
    // 6) FC1 + exact GELU
    gemm_mma<1><<<dim3(MT, 4), 256, GSMEM>>>(ln2b, wfc1, fc1_b, h1, MTOT, HID, CC, nullptr);
    // 7) FC2 + residual -> out
    gemm_mma<2><<<dim3(MT, 1), 256, GSMEM>>>(h1, wfc2, fc2_b, out, MTOT, CC, HID, x2);
}